// round 14
// baseline (speedup 1.0000x reference)
#include <cuda_runtime.h>
#include <stdint.h>
#include <math.h>

#define S_LEN 2048
#define HID   2048
#define NH    32
#define NKV   8
#define HD    64
#define DQ    (NH * HD)    // 2048
#define DKV   (NKV * HD)   // 512
#define DQKV  (DQ + 2 * DKV)
#define NEG_HUGE (-1e30f)

// -------- scratch (no dynamic allocation allowed) --------
__device__ float g_q[S_LEN * DQ];       // 16 MB  tf32 bits
__device__ float g_k[S_LEN * DKV];      //  4 MB  tf32 bits
__device__ float g_v[S_LEN * DKV];      //  4 MB  tf32 bits
__device__ float g_o[S_LEN * DQ];       // 16 MB  tf32 bits
__device__ float g_hsT[S_LEN * HID];    // 16 MB  tf32(hs)
__device__ float g_wqkvT[DQKV * HID];   // 24 MB  tf32(wq|wk|wv)
__device__ float g_woT[HID * HID];      // 16 MB  tf32(wo)

// ============================================================
// TF32 helpers
// ============================================================
__device__ __forceinline__ uint32_t f2tf32(float x) {
    uint32_t u;
    asm("cvt.rna.tf32.f32 %0, %1;" : "=r"(u) : "f"(x));
    return u;
}

__device__ __forceinline__ void mma_tf32(float c[4], const uint32_t a[4], const uint32_t b[2]) {
    asm volatile(
        "mma.sync.aligned.m16n8k8.row.col.f32.tf32.tf32.f32 "
        "{%0,%1,%2,%3}, {%4,%5,%6,%7}, {%8,%9}, {%0,%1,%2,%3};"
        : "+f"(c[0]), "+f"(c[1]), "+f"(c[2]), "+f"(c[3])
        : "r"(a[0]), "r"(a[1]), "r"(a[2]), "r"(a[3]),
          "r"(b[0]), "r"(b[1]));
}

__device__ __forceinline__ void cp_async16(uint32_t smem_dst, const void* gmem_src) {
    asm volatile("cp.async.cg.shared.global [%0], [%1], 16;" :: "r"(smem_dst), "l"(gmem_src));
}

// ============================================================
// Fused one-shot fp32 -> tf32-bits conversion for all 5 tensors
// (segments by float4 index; one launch instead of five)
// ============================================================
#define CVT_HS  (S_LEN * HID / 4)              // 1048576
#define CVT_WQ  (CVT_HS + DQ * HID / 4)        // 2097152
#define CVT_WK  (CVT_WQ + DKV * HID / 4)       // 2359296
#define CVT_WV  (CVT_WK + DKV * HID / 4)       // 2621440
#define CVT_ALL (CVT_WV + HID * HID / 4)       // 3670016

__global__ void cvt_all(const float* __restrict__ hs,
                        const float* __restrict__ wq,
                        const float* __restrict__ wk,
                        const float* __restrict__ wv,
                        const float* __restrict__ wo) {
    int i = blockIdx.x * blockDim.x + threadIdx.x;
    if (i >= CVT_ALL) return;
    const float* src;
    float* dst;
    int local;
    if (i < CVT_HS)      { src = hs; dst = g_hsT;  local = i; }
    else if (i < CVT_WQ) { src = wq; dst = g_wqkvT; local = i - CVT_HS; }
    else if (i < CVT_WK) { src = wk; dst = g_wqkvT + (size_t)DQ * HID;          local = i - CVT_WQ; }
    else if (i < CVT_WV) { src = wv; dst = g_wqkvT + (size_t)(DQ + DKV) * HID;  local = i - CVT_WK; }
    else                 { src = wo; dst = g_woT;  local = i - CVT_WV; }
    float4 v = reinterpret_cast<const float4*>(src)[local];
    uint4 u;
    u.x = f2tf32(v.x); u.y = f2tf32(v.y); u.z = f2tf32(v.z); u.w = f2tf32(v.w);
    reinterpret_cast<uint4*>(dst)[local] = u;
}

#define GK_PAD 36
#define GK_TILE (128 * GK_PAD)

// ============================================================
// Fused QKV projection + RoPE + scaling (byte-exact R8 version)
// ============================================================
__global__ __launch_bounds__(256) void qkv_gemm(const float* __restrict__ cosb,
                                                const float* __restrict__ sinb) {
    extern __shared__ float sm[];
    const int tid    = threadIdx.x;
    const int lane   = tid & 31;
    const int wid    = tid >> 5;
    const int warp_m = wid & 3;
    const int warp_n = wid >> 2;
    const int g      = lane >> 2;
    const int cg     = lane & 3;
    const int brow   = blockIdx.y * 128;
    const int bcol   = blockIdx.x * 128;

    const int seg = (bcol < DQ) ? 0 : ((bcol < DQ + DKV) ? 1 : 2);
    const int segbase = (seg == 0) ? 0 : ((seg == 1) ? DQ : DQ + DKV);
    const int out_col = bcol - segbase;
    const int out_ld  = (seg == 0) ? DQ : DKV;
    const bool do_rope = (seg != 2);
    const float scale  = (seg == 0) ? 0.125f : 1.0f;
    float* out = (seg == 0) ? g_q : (seg == 1) ? g_k : g_v;

    float acc[2][8][4];
#pragma unroll
    for (int i = 0; i < 2; i++)
#pragma unroll
        for (int j = 0; j < 8; j++)
#pragma unroll
            for (int t = 0; t < 4; t++) acc[i][j][t] = 0.f;

    auto prefetch = [&](int stage, int k0) {
        float* As = sm + stage * (2 * GK_TILE);
        float* Bs = As + GK_TILE;
        uint32_t as_base = (uint32_t)__cvta_generic_to_shared(As);
        uint32_t bs_base = (uint32_t)__cvta_generic_to_shared(Bs);
#pragma unroll
        for (int i = 0; i < 4; i++) {
            int idx = i * 256 + tid;
            int r   = idx >> 3;
            int c4  = idx & 7;
            cp_async16(as_base + (r * GK_PAD + c4 * 4) * 4,
                       &g_hsT[(size_t)(brow + r) * HID + k0 + c4 * 4]);
            cp_async16(bs_base + (r * GK_PAD + c4 * 4) * 4,
                       &g_wqkvT[(size_t)(bcol + r) * HID + k0 + c4 * 4]);
        }
        asm volatile("cp.async.commit_group;");
    };

    int stage = 0;
    prefetch(0, 0);

    for (int k0 = 0; k0 < HID; k0 += 32) {
        const bool has_next = (k0 + 32) < HID;
        if (has_next) prefetch(stage ^ 1, k0 + 32);

        if (has_next) asm volatile("cp.async.wait_group 1;");
        else          asm volatile("cp.async.wait_group 0;");
        __syncthreads();

        const uint32_t* As = reinterpret_cast<const uint32_t*>(sm + stage * (2 * GK_TILE));
        const uint32_t* Bs = As + GK_TILE;

#pragma unroll
        for (int kk = 0; kk < 4; kk++) {
            const int kb = kk * 8;
            uint32_t Af[2][4], Bf[8][2];
#pragma unroll
            for (int mt = 0; mt < 2; mt++) {
                const uint32_t* p = &As[(warp_m * 32 + mt * 16 + g) * GK_PAD + kb + cg];
                Af[mt][0] = p[0];
                Af[mt][1] = p[8 * GK_PAD];
                Af[mt][2] = p[4];
                Af[mt][3] = p[8 * GK_PAD + 4];
            }
#pragma unroll
            for (int nt = 0; nt < 8; nt++) {
                const uint32_t* p = &Bs[(warp_n * 64 + nt * 8 + g) * GK_PAD + kb + cg];
                Bf[nt][0] = p[0];
                Bf[nt][1] = p[4];
            }
#pragma unroll
            for (int mt = 0; mt < 2; mt++)
#pragma unroll
                for (int nt = 0; nt < 8; nt++)
                    mma_tf32(acc[mt][nt], Af[mt], Bf[nt]);
        }
        __syncthreads();
        stage ^= 1;
    }

#pragma unroll
    for (int mt = 0; mt < 2; mt++) {
        const int r0 = brow + warp_m * 32 + mt * 16 + g;
        if (do_rope) {
            const float* cb0 = cosb + r0 * HD;
            const float* sb0 = sinb + r0 * HD;
            const float* cb1 = cosb + (r0 + 8) * HD;
            const float* sb1 = sinb + (r0 + 8) * HD;
#pragma unroll
            for (int nt = 0; nt < 4; nt++) {
                const int d = nt * 8 + 2 * cg;
#pragma unroll
                for (int e = 0; e < 2; e++) {
                    const float cl0 = __ldg(cb0 + d + e);
                    const float sl0 = __ldg(sb0 + d + e);
                    const float ch0 = __ldg(cb0 + d + e + 32);
                    const float sh0 = __ldg(sb0 + d + e + 32);
                    const float cl1 = __ldg(cb1 + d + e);
                    const float sl1 = __ldg(sb1 + d + e);
                    const float ch1 = __ldg(cb1 + d + e + 32);
                    const float sh1 = __ldg(sb1 + d + e + 32);

                    const float x1 = acc[mt][nt][e],     x2 = acc[mt][nt + 4][e];
                    acc[mt][nt][e]     = (x1 * cl0 - x2 * sl0) * scale;
                    acc[mt][nt + 4][e] = (x2 * ch0 + x1 * sh0) * scale;
                    const float y1 = acc[mt][nt][e + 2], y2 = acc[mt][nt + 4][e + 2];
                    acc[mt][nt][e + 2]     = (y1 * cl1 - y2 * sl1) * scale;
                    acc[mt][nt + 4][e + 2] = (y2 * ch1 + y1 * sh1) * scale;
                }
            }
        }
        float* orow0 = out + (size_t)r0 * out_ld + out_col + warp_n * 64;
        float* orow1 = orow0 + (size_t)8 * out_ld;
#pragma unroll
        for (int nt = 0; nt < 8; nt++) {
            const int c = nt * 8 + 2 * cg;
            *reinterpret_cast<float2*>(orow0 + c) =
                make_float2(__uint_as_float(f2tf32(acc[mt][nt][0])),
                            __uint_as_float(f2tf32(acc[mt][nt][1])));
            *reinterpret_cast<float2*>(orow1 + c) =
                make_float2(__uint_as_float(f2tf32(acc[mt][nt][2])),
                            __uint_as_float(f2tf32(acc[mt][nt][3])));
        }
    }
}

// ============================================================
// O-projection: C = A * B^T, tf32 bits in, fp32 out (R8 version)
// ============================================================
__global__ __launch_bounds__(256) void gemm_tf32(const float* __restrict__ A,
                                                 const float* __restrict__ B,
                                                 float* __restrict__ C,
                                                 int M, int N, int K) {
    extern __shared__ float sm[];
    const int tid    = threadIdx.x;
    const int lane   = tid & 31;
    const int wid    = tid >> 5;
    const int warp_m = wid >> 2;
    const int warp_n = wid & 3;
    const int g      = lane >> 2;
    const int cg     = lane & 3;
    const int brow   = blockIdx.y * 128;
    const int bcol   = blockIdx.x * 128;

    float acc[4][4][4];
#pragma unroll
    for (int i = 0; i < 4; i++)
#pragma unroll
        for (int j = 0; j < 4; j++)
#pragma unroll
            for (int t = 0; t < 4; t++) acc[i][j][t] = 0.f;

    auto prefetch = [&](int stage, int k0) {
        float* As = sm + stage * (2 * GK_TILE);
        float* Bs = As + GK_TILE;
        uint32_t as_base = (uint32_t)__cvta_generic_to_shared(As);
        uint32_t bs_base = (uint32_t)__cvta_generic_to_shared(Bs);
#pragma unroll
        for (int i = 0; i < 4; i++) {
            int idx = i * 256 + tid;
            int r   = idx >> 3;
            int c4  = idx & 7;
            cp_async16(as_base + (r * GK_PAD + c4 * 4) * 4,
                       &A[(size_t)(brow + r) * K + k0 + c4 * 4]);
            cp_async16(bs_base + (r * GK_PAD + c4 * 4) * 4,
                       &B[(size_t)(bcol + r) * K + k0 + c4 * 4]);
        }
        asm volatile("cp.async.commit_group;");
    };

    int stage = 0;
    prefetch(0, 0);

    for (int k0 = 0; k0 < K; k0 += 32) {
        const bool has_next = (k0 + 32) < K;
        if (has_next) prefetch(stage ^ 1, k0 + 32);

        if (has_next) asm volatile("cp.async.wait_group 1;");
        else          asm volatile("cp.async.wait_group 0;");
        __syncthreads();

        const uint32_t* As = reinterpret_cast<const uint32_t*>(sm + stage * (2 * GK_TILE));
        const uint32_t* Bs = As + GK_TILE;

#pragma unroll
        for (int kk = 0; kk < 4; kk++) {
            const int kb = kk * 8;
            uint32_t Af[4][4], Bf[4][2];
#pragma unroll
            for (int mt = 0; mt < 4; mt++) {
                const uint32_t* p = &As[(warp_m * 64 + mt * 16 + g) * GK_PAD + kb + cg];
                Af[mt][0] = p[0];
                Af[mt][1] = p[8 * GK_PAD];
                Af[mt][2] = p[4];
                Af[mt][3] = p[8 * GK_PAD + 4];
            }
#pragma unroll
            for (int nt = 0; nt < 4; nt++) {
                const uint32_t* p = &Bs[(warp_n * 32 + nt * 8 + g) * GK_PAD + kb + cg];
                Bf[nt][0] = p[0];
                Bf[nt][1] = p[4];
            }
#pragma unroll
            for (int mt = 0; mt < 4; mt++)
#pragma unroll
                for (int nt = 0; nt < 4; nt++)
                    mma_tf32(acc[mt][nt], Af[mt], Bf[nt]);
        }
        __syncthreads();
        stage ^= 1;
    }

#pragma unroll
    for (int mt = 0; mt < 4; mt++) {
#pragma unroll
        for (int nt = 0; nt < 4; nt++) {
            int row0 = brow + warp_m * 64 + mt * 16 + g;
            int col  = bcol + warp_n * 32 + nt * 8 + 2 * cg;
            float2 v0 = make_float2(acc[mt][nt][0], acc[mt][nt][1]);
            float2 v1 = make_float2(acc[mt][nt][2], acc[mt][nt][3]);
            *reinterpret_cast<float2*>(&C[(size_t)row0 * N + col])       = v0;
            *reinterpret_cast<float2*>(&C[(size_t)(row0 + 8) * N + col]) = v1;
        }
    }
}

// ============================================================
// TF32 flash attention, BQ=64, 128 threads (4 warps), 3 CTA/SM.
// Same per-row k-block sequence as R8 -> identical numerics.
// ============================================================
#define KS_STR 68
#define VS_STR 72
#define FSTAGE (64 * KS_STR + 64 * VS_STR)

__global__ __launch_bounds__(128) void flash_tf32() {
    extern __shared__ float sm[];
    const int tid  = threadIdx.x;
    const int lane = tid & 31;
    const int w    = tid >> 5;          // 0..3
    const int g    = lane >> 2;
    const int cg   = lane & 3;
    const int qt   = gridDim.x - 1 - blockIdx.x;   // heavy tiles first
    const int head = blockIdx.y;
    const int kvh  = head >> 2;
    const int row0 = qt * 64 + w * 16 + g;

    uint32_t qf[8][4];
    {
        const uint32_t* q0 = reinterpret_cast<const uint32_t*>(&g_q[(size_t)row0 * DQ + head * HD]);
        const uint32_t* q1 = q0 + 8 * DQ;
#pragma unroll
        for (int ks = 0; ks < 8; ks++) {
            qf[ks][0] = q0[8 * ks + cg];
            qf[ks][1] = q1[8 * ks + cg];
            qf[ks][2] = q0[8 * ks + cg + 4];
            qf[ks][3] = q1[8 * ks + cg + 4];
        }
    }

    float oacc[8][4];
#pragma unroll
    for (int nf = 0; nf < 8; nf++)
#pragma unroll
        for (int t = 0; t < 4; t++) oacc[nf][t] = 0.f;
    float m0 = NEG_HUGE, m1 = NEG_HUGE, l0 = 0.f, l1 = 0.f;

    auto prefetch = [&](int kb, int s) {
        float* Ks = sm + s * FSTAGE;
        float* Vs = Ks + 64 * KS_STR;
        uint32_t ka = (uint32_t)__cvta_generic_to_shared(Ks);
        uint32_t va = (uint32_t)__cvta_generic_to_shared(Vs);
#pragma unroll
        for (int t = 0; t < 8; t++) {
            int idx = t * 128 + tid;     // 0..1023
            int r   = idx >> 4;          // 0..63
            int c4  = (idx & 15) * 4;    // 0..60
            cp_async16(ka + (r * KS_STR + c4) * 4,
                       &g_k[(size_t)(kb * 64 + r) * DKV + kvh * HD + c4]);
            cp_async16(va + (r * VS_STR + c4) * 4,
                       &g_v[(size_t)(kb * 64 + r) * DKV + kvh * HD + c4]);
        }
        asm volatile("cp.async.commit_group;");
    };

    const int nkb = qt + 1;
    prefetch(0, 0);

    for (int kb = 0; kb < nkb; kb++) {
        const int s = kb & 1;
        if (kb + 1 < nkb) {
            prefetch(kb + 1, s ^ 1);
            asm volatile("cp.async.wait_group 1;");
        } else {
            asm volatile("cp.async.wait_group 0;");
        }
        __syncthreads();

        const uint32_t* Ks = reinterpret_cast<const uint32_t*>(sm + s * FSTAGE);
        const uint32_t* Vs = Ks + 64 * KS_STR;

        float sacc[8][4];
#pragma unroll
        for (int nf = 0; nf < 8; nf++)
#pragma unroll
            for (int t = 0; t < 4; t++) sacc[nf][t] = 0.f;

#pragma unroll
        for (int ks = 0; ks < 8; ks++) {
#pragma unroll
            for (int nf = 0; nf < 8; nf++) {
                uint32_t b[2];
                const uint32_t* p = &Ks[(nf * 8 + g) * KS_STR + ks * 8 + cg];
                b[0] = p[0];
                b[1] = p[4];
                mma_tf32(sacc[nf], qf[ks], b);
            }
        }

        if (kb == qt) {   // diagonal block: causal mask
#pragma unroll
            for (int nf = 0; nf < 8; nf++) {
                int c = kb * 64 + nf * 8 + 2 * cg;
                if (c     > row0)     sacc[nf][0] = NEG_HUGE;
                if (c + 1 > row0)     sacc[nf][1] = NEG_HUGE;
                if (c     > row0 + 8) sacc[nf][2] = NEG_HUGE;
                if (c + 1 > row0 + 8) sacc[nf][3] = NEG_HUGE;
            }
        }

        float tm0 = NEG_HUGE, tm1 = NEG_HUGE;
#pragma unroll
        for (int nf = 0; nf < 8; nf++) {
            tm0 = fmaxf(tm0, fmaxf(sacc[nf][0], sacc[nf][1]));
            tm1 = fmaxf(tm1, fmaxf(sacc[nf][2], sacc[nf][3]));
        }
        tm0 = fmaxf(tm0, __shfl_xor_sync(0xffffffff, tm0, 1));
        tm0 = fmaxf(tm0, __shfl_xor_sync(0xffffffff, tm0, 2));
        tm1 = fmaxf(tm1, __shfl_xor_sync(0xffffffff, tm1, 1));
        tm1 = fmaxf(tm1, __shfl_xor_sync(0xffffffff, tm1, 2));

        const float mn0 = fmaxf(m0, tm0);
        const float mn1 = fmaxf(m1, tm1);
        const float sc0 = __expf(m0 - mn0);
        const float sc1 = __expf(m1 - mn1);

        float rs0 = 0.f, rs1 = 0.f;
#pragma unroll
        for (int nf = 0; nf < 8; nf++) {
            sacc[nf][0] = __expf(sacc[nf][0] - mn0);
            sacc[nf][1] = __expf(sacc[nf][1] - mn0);
            sacc[nf][2] = __expf(sacc[nf][2] - mn1);
            sacc[nf][3] = __expf(sacc[nf][3] - mn1);
            rs0 += sacc[nf][0] + sacc[nf][1];
            rs1 += sacc[nf][2] + sacc[nf][3];
        }
        rs0 += __shfl_xor_sync(0xffffffff, rs0, 1);
        rs0 += __shfl_xor_sync(0xffffffff, rs0, 2);
        rs1 += __shfl_xor_sync(0xffffffff, rs1, 1);
        rs1 += __shfl_xor_sync(0xffffffff, rs1, 2);

        l0 = l0 * sc0 + rs0;  m0 = mn0;
        l1 = l1 * sc1 + rs1;  m1 = mn1;
#pragma unroll
        for (int nf = 0; nf < 8; nf++) {
            oacc[nf][0] *= sc0; oacc[nf][1] *= sc0;
            oacc[nf][2] *= sc1; oacc[nf][3] *= sc1;
        }

        const int base = lane & ~3;
        const int s0l  = base + (cg >> 1);
        const int s1l  = s0l + 2;
        const bool odd = (cg & 1);
#pragma unroll
        for (int ks = 0; ks < 8; ks++) {
            const uint32_t c0 = f2tf32(sacc[ks][0]);
            const uint32_t c1 = f2tf32(sacc[ks][1]);
            const uint32_t c2 = f2tf32(sacc[ks][2]);
            const uint32_t c3 = f2tf32(sacc[ks][3]);
            uint32_t a[4];
            {
                uint32_t t00 = __shfl_sync(0xffffffff, c0, s0l);
                uint32_t t01 = __shfl_sync(0xffffffff, c1, s0l);
                uint32_t t10 = __shfl_sync(0xffffffff, c0, s1l);
                uint32_t t11 = __shfl_sync(0xffffffff, c1, s1l);
                a[0] = odd ? t01 : t00;
                a[2] = odd ? t11 : t10;
                uint32_t u00 = __shfl_sync(0xffffffff, c2, s0l);
                uint32_t u01 = __shfl_sync(0xffffffff, c3, s0l);
                uint32_t u10 = __shfl_sync(0xffffffff, c2, s1l);
                uint32_t u11 = __shfl_sync(0xffffffff, c3, s1l);
                a[1] = odd ? u01 : u00;
                a[3] = odd ? u11 : u10;
            }
#pragma unroll
            for (int nf = 0; nf < 8; nf++) {
                uint32_t b[2];
                const uint32_t* vp = &Vs[(ks * 8 + cg) * VS_STR + nf * 8 + g];
                b[0] = vp[0];
                b[1] = vp[4 * VS_STR];
                mma_tf32(oacc[nf], a, b);
            }
        }
        __syncthreads();
    }

    const float inv0 = 1.f / l0;
    const float inv1 = 1.f / l1;
    float* o0 = &g_o[(size_t)row0 * DQ + head * HD];
    float* o1 = o0 + 8 * DQ;
#pragma unroll
    for (int nf = 0; nf < 8; nf++) {
        *reinterpret_cast<float2*>(&o0[nf * 8 + 2 * cg]) =
            make_float2(__uint_as_float(f2tf32(oacc[nf][0] * inv0)),
                        __uint_as_float(f2tf32(oacc[nf][1] * inv0)));
        *reinterpret_cast<float2*>(&o1[nf * 8 + 2 * cg]) =
            make_float2(__uint_as_float(f2tf32(oacc[nf][2] * inv1)),
                        __uint_as_float(f2tf32(oacc[nf][3] * inv1)));
    }
}

// ============================================================
extern "C" void kernel_launch(void* const* d_in, const int* in_sizes, int n_in,
                              void* d_out, int out_size) {
    const float* hs   = (const float*)d_in[0];
    const float* cosb = (const float*)d_in[1];
    const float* sinb = (const float*)d_in[2];
    // d_in[3] = attention_mask (causal) — implemented analytically
    const float* wq   = (const float*)d_in[4];
    const float* wk   = (const float*)d_in[5];
    const float* wv   = (const float*)d_in[6];
    const float* wo   = (const float*)d_in[7];
    float* out = (float*)d_out;

    float *op, *woT;
    cudaGetSymbolAddress((void**)&op,  g_o);
    cudaGetSymbolAddress((void**)&woT, g_woT);

    const int gemm_smem  = 2 * 2 * GK_TILE * (int)sizeof(float);   // 73728 B
    const int flash_smem = 2 * FSTAGE * (int)sizeof(float);        // 71680 B
    cudaFuncSetAttribute(qkv_gemm,   cudaFuncAttributeMaxDynamicSharedMemorySize, gemm_smem);
    cudaFuncSetAttribute(gemm_tf32,  cudaFuncAttributeMaxDynamicSharedMemorySize, gemm_smem);
    cudaFuncSetAttribute(flash_tf32, cudaFuncAttributeMaxDynamicSharedMemorySize, flash_smem);

    // single fused fp32 -> tf32-bits conversion
    const int CB = 256;
    cvt_all<<<(CVT_ALL + CB - 1) / CB, CB>>>(hs, wq, wk, wv, wo);

    // fused QKV projection + RoPE + scale
    qkv_gemm<<<dim3(DQKV / 128, S_LEN / 128), 256, gemm_smem>>>(cosb, sinb);

    // TF32 causal flash attention: BQ=64, 4 warps, 3 CTA/SM
    flash_tf32<<<dim3(S_LEN / 64, NH), 128, flash_smem>>>();

    // output projection
    gemm_tf32<<<dim3(HID / 128, S_LEN / 128), 256, gemm_smem>>>(op, woT, out, S_LEN, HID, HID);
}

// round 15
// speedup vs baseline: 1.0160x; 1.0160x over previous
#include <cuda_runtime.h>
#include <stdint.h>
#include <math.h>

#define S_LEN 2048
#define HID   2048
#define NH    32
#define NKV   8
#define HD    64
#define DQ    (NH * HD)    // 2048
#define DKV   (NKV * HD)   // 512
#define DQKV  (DQ + 2 * DKV)
#define NEG_HUGE (-1e30f)

// -------- scratch (no dynamic allocation allowed) --------
__device__ float g_q[S_LEN * DQ];       // 16 MB  tf32 bits
__device__ float g_k[S_LEN * DKV];      //  4 MB  tf32 bits
__device__ float g_v[S_LEN * DKV];      //  4 MB  tf32 bits
__device__ float g_o[S_LEN * DQ];       // 16 MB  tf32 bits
__device__ float g_hsT[S_LEN * HID];    // 16 MB  tf32(hs)
__device__ float g_wqkvT[DQKV * HID];   // 24 MB  tf32(wq|wk|wv)
__device__ float g_woT[HID * HID];      // 16 MB  tf32(wo)

// ============================================================
// TF32 helpers
// ============================================================
__device__ __forceinline__ uint32_t f2tf32(float x) {
    uint32_t u;
    asm("cvt.rna.tf32.f32 %0, %1;" : "=r"(u) : "f"(x));
    return u;
}

__device__ __forceinline__ void mma_tf32(float c[4], const uint32_t a[4], const uint32_t b[2]) {
    asm volatile(
        "mma.sync.aligned.m16n8k8.row.col.f32.tf32.tf32.f32 "
        "{%0,%1,%2,%3}, {%4,%5,%6,%7}, {%8,%9}, {%0,%1,%2,%3};"
        : "+f"(c[0]), "+f"(c[1]), "+f"(c[2]), "+f"(c[3])
        : "r"(a[0]), "r"(a[1]), "r"(a[2]), "r"(a[3]),
          "r"(b[0]), "r"(b[1]));
}

__device__ __forceinline__ void cp_async16(uint32_t smem_dst, const void* gmem_src) {
    asm volatile("cp.async.cg.shared.global [%0], [%1], 16;" :: "r"(smem_dst), "l"(gmem_src));
}

// ============================================================
// Fused one-shot fp32 -> tf32-bits conversion for all 5 tensors
// ============================================================
#define CVT_HS  (S_LEN * HID / 4)
#define CVT_WQ  (CVT_HS + DQ * HID / 4)
#define CVT_WK  (CVT_WQ + DKV * HID / 4)
#define CVT_WV  (CVT_WK + DKV * HID / 4)
#define CVT_ALL (CVT_WV + HID * HID / 4)

__global__ void cvt_all(const float* __restrict__ hs,
                        const float* __restrict__ wq,
                        const float* __restrict__ wk,
                        const float* __restrict__ wv,
                        const float* __restrict__ wo) {
    int i = blockIdx.x * blockDim.x + threadIdx.x;
    if (i >= CVT_ALL) return;
    const float* src;
    float* dst;
    int local;
    if (i < CVT_HS)      { src = hs; dst = g_hsT;  local = i; }
    else if (i < CVT_WQ) { src = wq; dst = g_wqkvT; local = i - CVT_HS; }
    else if (i < CVT_WK) { src = wk; dst = g_wqkvT + (size_t)DQ * HID;          local = i - CVT_WQ; }
    else if (i < CVT_WV) { src = wv; dst = g_wqkvT + (size_t)(DQ + DKV) * HID;  local = i - CVT_WK; }
    else                 { src = wo; dst = g_woT;  local = i - CVT_WV; }
    float4 v = reinterpret_cast<const float4*>(src)[local];
    uint4 u;
    u.x = f2tf32(v.x); u.y = f2tf32(v.y); u.z = f2tf32(v.z); u.w = f2tf32(v.w);
    reinterpret_cast<uint4*>(dst)[local] = u;
}

#define GK_PAD 36
#define GK_TILE (128 * GK_PAD)
#define GK_STAGES 3

// ============================================================
// Fused QKV projection + RoPE + scaling.
// 3-stage cp.async ring, ONE __syncthreads per K-iteration.
// ============================================================
__global__ __launch_bounds__(256) void qkv_gemm(const float* __restrict__ cosb,
                                                const float* __restrict__ sinb) {
    extern __shared__ float sm[];
    const int tid    = threadIdx.x;
    const int lane   = tid & 31;
    const int wid    = tid >> 5;
    const int warp_m = wid & 3;
    const int warp_n = wid >> 2;
    const int g      = lane >> 2;
    const int cg     = lane & 3;
    const int brow   = blockIdx.y * 128;
    const int bcol   = blockIdx.x * 128;

    const int seg = (bcol < DQ) ? 0 : ((bcol < DQ + DKV) ? 1 : 2);
    const int segbase = (seg == 0) ? 0 : ((seg == 1) ? DQ : DQ + DKV);
    const int out_col = bcol - segbase;
    const int out_ld  = (seg == 0) ? DQ : DKV;
    const bool do_rope = (seg != 2);
    const float scale  = (seg == 0) ? 0.125f : 1.0f;
    float* out = (seg == 0) ? g_q : (seg == 1) ? g_k : g_v;

    float acc[2][8][4];
#pragma unroll
    for (int i = 0; i < 2; i++)
#pragma unroll
        for (int j = 0; j < 8; j++)
#pragma unroll
            for (int t = 0; t < 4; t++) acc[i][j][t] = 0.f;

    auto prefetch = [&](int s, int tile) {
        float* As = sm + s * (2 * GK_TILE);
        float* Bs = As + GK_TILE;
        uint32_t as_base = (uint32_t)__cvta_generic_to_shared(As);
        uint32_t bs_base = (uint32_t)__cvta_generic_to_shared(Bs);
        const int k0 = tile * 32;
#pragma unroll
        for (int i = 0; i < 4; i++) {
            int idx = i * 256 + tid;
            int r   = idx >> 3;
            int c4  = idx & 7;
            cp_async16(as_base + (r * GK_PAD + c4 * 4) * 4,
                       &g_hsT[(size_t)(brow + r) * HID + k0 + c4 * 4]);
            cp_async16(bs_base + (r * GK_PAD + c4 * 4) * 4,
                       &g_wqkvT[(size_t)(bcol + r) * HID + k0 + c4 * 4]);
        }
        asm volatile("cp.async.commit_group;");
    };

    const int NT = HID / 32;   // 64
    prefetch(0, 0);
    prefetch(1, 1);

    for (int i = 0; i < NT; i++) {
        const int s = i % GK_STAGES;
        if (i + 1 < NT) asm volatile("cp.async.wait_group 1;");
        else            asm volatile("cp.async.wait_group 0;");
        __syncthreads();
        if (i + 2 < NT) prefetch((i + 2) % GK_STAGES, i + 2);

        const uint32_t* As = reinterpret_cast<const uint32_t*>(sm + s * (2 * GK_TILE));
        const uint32_t* Bs = As + GK_TILE;

#pragma unroll
        for (int kk = 0; kk < 4; kk++) {
            const int kb = kk * 8;
            uint32_t Af[2][4], Bf[8][2];
#pragma unroll
            for (int mt = 0; mt < 2; mt++) {
                const uint32_t* p = &As[(warp_m * 32 + mt * 16 + g) * GK_PAD + kb + cg];
                Af[mt][0] = p[0];
                Af[mt][1] = p[8 * GK_PAD];
                Af[mt][2] = p[4];
                Af[mt][3] = p[8 * GK_PAD + 4];
            }
#pragma unroll
            for (int nt = 0; nt < 8; nt++) {
                const uint32_t* p = &Bs[(warp_n * 64 + nt * 8 + g) * GK_PAD + kb + cg];
                Bf[nt][0] = p[0];
                Bf[nt][1] = p[4];
            }
#pragma unroll
            for (int mt = 0; mt < 2; mt++)
#pragma unroll
                for (int nt = 0; nt < 8; nt++)
                    mma_tf32(acc[mt][nt], Af[mt], Bf[nt]);
        }
    }

#pragma unroll
    for (int mt = 0; mt < 2; mt++) {
        const int r0 = brow + warp_m * 32 + mt * 16 + g;
        if (do_rope) {
            const float* cb0 = cosb + r0 * HD;
            const float* sb0 = sinb + r0 * HD;
            const float* cb1 = cosb + (r0 + 8) * HD;
            const float* sb1 = sinb + (r0 + 8) * HD;
#pragma unroll
            for (int nt = 0; nt < 4; nt++) {
                const int d = nt * 8 + 2 * cg;
#pragma unroll
                for (int e = 0; e < 2; e++) {
                    const float cl0 = __ldg(cb0 + d + e);
                    const float sl0 = __ldg(sb0 + d + e);
                    const float ch0 = __ldg(cb0 + d + e + 32);
                    const float sh0 = __ldg(sb0 + d + e + 32);
                    const float cl1 = __ldg(cb1 + d + e);
                    const float sl1 = __ldg(sb1 + d + e);
                    const float ch1 = __ldg(cb1 + d + e + 32);
                    const float sh1 = __ldg(sb1 + d + e + 32);

                    const float x1 = acc[mt][nt][e],     x2 = acc[mt][nt + 4][e];
                    acc[mt][nt][e]     = (x1 * cl0 - x2 * sl0) * scale;
                    acc[mt][nt + 4][e] = (x2 * ch0 + x1 * sh0) * scale;
                    const float y1 = acc[mt][nt][e + 2], y2 = acc[mt][nt + 4][e + 2];
                    acc[mt][nt][e + 2]     = (y1 * cl1 - y2 * sl1) * scale;
                    acc[mt][nt + 4][e + 2] = (y2 * ch1 + y1 * sh1) * scale;
                }
            }
        }
        float* orow0 = out + (size_t)r0 * out_ld + out_col + warp_n * 64;
        float* orow1 = orow0 + (size_t)8 * out_ld;
#pragma unroll
        for (int nt = 0; nt < 8; nt++) {
            const int c = nt * 8 + 2 * cg;
            *reinterpret_cast<float2*>(orow0 + c) =
                make_float2(__uint_as_float(f2tf32(acc[mt][nt][0])),
                            __uint_as_float(f2tf32(acc[mt][nt][1])));
            *reinterpret_cast<float2*>(orow1 + c) =
                make_float2(__uint_as_float(f2tf32(acc[mt][nt][2])),
                            __uint_as_float(f2tf32(acc[mt][nt][3])));
        }
    }
}

// ============================================================
// O-projection: C = A * B^T, tf32 bits in, fp32 out.
// 3-stage cp.async ring, ONE __syncthreads per K-iteration.
// ============================================================
__global__ __launch_bounds__(256) void gemm_tf32(const float* __restrict__ A,
                                                 const float* __restrict__ B,
                                                 float* __restrict__ C,
                                                 int M, int N, int K) {
    extern __shared__ float sm[];
    const int tid    = threadIdx.x;
    const int lane   = tid & 31;
    const int wid    = tid >> 5;
    const int warp_m = wid >> 2;
    const int warp_n = wid & 3;
    const int g      = lane >> 2;
    const int cg     = lane & 3;
    const int brow   = blockIdx.y * 128;
    const int bcol   = blockIdx.x * 128;

    float acc[4][4][4];
#pragma unroll
    for (int i = 0; i < 4; i++)
#pragma unroll
        for (int j = 0; j < 4; j++)
#pragma unroll
            for (int t = 0; t < 4; t++) acc[i][j][t] = 0.f;

    auto prefetch = [&](int s, int tile) {
        float* As = sm + s * (2 * GK_TILE);
        float* Bs = As + GK_TILE;
        uint32_t as_base = (uint32_t)__cvta_generic_to_shared(As);
        uint32_t bs_base = (uint32_t)__cvta_generic_to_shared(Bs);
        const int k0 = tile * 32;
#pragma unroll
        for (int i = 0; i < 4; i++) {
            int idx = i * 256 + tid;
            int r   = idx >> 3;
            int c4  = idx & 7;
            cp_async16(as_base + (r * GK_PAD + c4 * 4) * 4,
                       &A[(size_t)(brow + r) * K + k0 + c4 * 4]);
            cp_async16(bs_base + (r * GK_PAD + c4 * 4) * 4,
                       &B[(size_t)(bcol + r) * K + k0 + c4 * 4]);
        }
        asm volatile("cp.async.commit_group;");
    };

    const int NT = K / 32;
    prefetch(0, 0);
    prefetch(1, 1);

    for (int i = 0; i < NT; i++) {
        const int s = i % GK_STAGES;
        if (i + 1 < NT) asm volatile("cp.async.wait_group 1;");
        else            asm volatile("cp.async.wait_group 0;");
        __syncthreads();
        if (i + 2 < NT) prefetch((i + 2) % GK_STAGES, i + 2);

        const uint32_t* As = reinterpret_cast<const uint32_t*>(sm + s * (2 * GK_TILE));
        const uint32_t* Bs = As + GK_TILE;

#pragma unroll
        for (int kk = 0; kk < 4; kk++) {
            const int kb = kk * 8;
            uint32_t Af[4][4], Bf[4][2];
#pragma unroll
            for (int mt = 0; mt < 4; mt++) {
                const uint32_t* p = &As[(warp_m * 64 + mt * 16 + g) * GK_PAD + kb + cg];
                Af[mt][0] = p[0];
                Af[mt][1] = p[8 * GK_PAD];
                Af[mt][2] = p[4];
                Af[mt][3] = p[8 * GK_PAD + 4];
            }
#pragma unroll
            for (int nt = 0; nt < 4; nt++) {
                const uint32_t* p = &Bs[(warp_n * 32 + nt * 8 + g) * GK_PAD + kb + cg];
                Bf[nt][0] = p[0];
                Bf[nt][1] = p[4];
            }
#pragma unroll
            for (int mt = 0; mt < 4; mt++)
#pragma unroll
                for (int nt = 0; nt < 4; nt++)
                    mma_tf32(acc[mt][nt], Af[mt], Bf[nt]);
        }
    }

#pragma unroll
    for (int mt = 0; mt < 4; mt++) {
#pragma unroll
        for (int nt = 0; nt < 4; nt++) {
            int row0 = brow + warp_m * 64 + mt * 16 + g;
            int col  = bcol + warp_n * 32 + nt * 8 + 2 * cg;
            float2 v0 = make_float2(acc[mt][nt][0], acc[mt][nt][1]);
            float2 v1 = make_float2(acc[mt][nt][2], acc[mt][nt][3]);
            *reinterpret_cast<float2*>(&C[(size_t)row0 * N + col])       = v0;
            *reinterpret_cast<float2*>(&C[(size_t)(row0 + 8) * N + col]) = v1;
        }
    }
}

// ============================================================
// TF32 flash attention (byte-exact R8 version, known-good)
// ============================================================
#define KS_STR 68
#define VS_STR 72
#define FSTAGE (64 * KS_STR + 64 * VS_STR)

__global__ __launch_bounds__(256) void flash_tf32() {
    extern __shared__ float sm[];
    const int tid  = threadIdx.x;
    const int lane = tid & 31;
    const int w    = tid >> 5;
    const int g    = lane >> 2;
    const int cg   = lane & 3;
    const int qt   = gridDim.x - 1 - blockIdx.x;
    const int head = blockIdx.y;
    const int kvh  = head >> 2;
    const int row0 = qt * 128 + w * 16 + g;

    uint32_t qf[8][4];
    {
        const uint32_t* q0 = reinterpret_cast<const uint32_t*>(&g_q[(size_t)row0 * DQ + head * HD]);
        const uint32_t* q1 = q0 + 8 * DQ;
#pragma unroll
        for (int ks = 0; ks < 8; ks++) {
            qf[ks][0] = q0[8 * ks + cg];
            qf[ks][1] = q1[8 * ks + cg];
            qf[ks][2] = q0[8 * ks + cg + 4];
            qf[ks][3] = q1[8 * ks + cg + 4];
        }
    }

    float oacc[8][4];
#pragma unroll
    for (int nf = 0; nf < 8; nf++)
#pragma unroll
        for (int t = 0; t < 4; t++) oacc[nf][t] = 0.f;
    float m0 = NEG_HUGE, m1 = NEG_HUGE, l0 = 0.f, l1 = 0.f;

    auto prefetch = [&](int kb, int s) {
        float* Ks = sm + s * FSTAGE;
        float* Vs = Ks + 64 * KS_STR;
        uint32_t ka = (uint32_t)__cvta_generic_to_shared(Ks);
        uint32_t va = (uint32_t)__cvta_generic_to_shared(Vs);
#pragma unroll
        for (int t = 0; t < 4; t++) {
            int idx = t * 256 + tid;
            int r   = idx >> 4;
            int c4  = (idx & 15) * 4;
            cp_async16(ka + (r * KS_STR + c4) * 4,
                       &g_k[(size_t)(kb * 64 + r) * DKV + kvh * HD + c4]);
            cp_async16(va + (r * VS_STR + c4) * 4,
                       &g_v[(size_t)(kb * 64 + r) * DKV + kvh * HD + c4]);
        }
        asm volatile("cp.async.commit_group;");
    };

    const int nkb = 2 * qt + 2;
    prefetch(0, 0);

    for (int kb = 0; kb < nkb; kb++) {
        const int s = kb & 1;
        if (kb + 1 < nkb) {
            prefetch(kb + 1, s ^ 1);
            asm volatile("cp.async.wait_group 1;");
        } else {
            asm volatile("cp.async.wait_group 0;");
        }
        __syncthreads();

        const uint32_t* Ks = reinterpret_cast<const uint32_t*>(sm + s * FSTAGE);
        const uint32_t* Vs = Ks + 64 * KS_STR;

        const bool active = !(w < 4 && kb == 2 * qt + 1);
        if (active) {
            float sacc[8][4];
#pragma unroll
            for (int nf = 0; nf < 8; nf++)
#pragma unroll
                for (int t = 0; t < 4; t++) sacc[nf][t] = 0.f;

#pragma unroll
            for (int ks = 0; ks < 8; ks++) {
#pragma unroll
                for (int nf = 0; nf < 8; nf++) {
                    uint32_t b[2];
                    const uint32_t* p = &Ks[(nf * 8 + g) * KS_STR + ks * 8 + cg];
                    b[0] = p[0];
                    b[1] = p[4];
                    mma_tf32(sacc[nf], qf[ks], b);
                }
            }

            if (kb >= 2 * qt) {
#pragma unroll
                for (int nf = 0; nf < 8; nf++) {
                    int c = kb * 64 + nf * 8 + 2 * cg;
                    if (c     > row0)     sacc[nf][0] = NEG_HUGE;
                    if (c + 1 > row0)     sacc[nf][1] = NEG_HUGE;
                    if (c     > row0 + 8) sacc[nf][2] = NEG_HUGE;
                    if (c + 1 > row0 + 8) sacc[nf][3] = NEG_HUGE;
                }
            }

            float tm0 = NEG_HUGE, tm1 = NEG_HUGE;
#pragma unroll
            for (int nf = 0; nf < 8; nf++) {
                tm0 = fmaxf(tm0, fmaxf(sacc[nf][0], sacc[nf][1]));
                tm1 = fmaxf(tm1, fmaxf(sacc[nf][2], sacc[nf][3]));
            }
            tm0 = fmaxf(tm0, __shfl_xor_sync(0xffffffff, tm0, 1));
            tm0 = fmaxf(tm0, __shfl_xor_sync(0xffffffff, tm0, 2));
            tm1 = fmaxf(tm1, __shfl_xor_sync(0xffffffff, tm1, 1));
            tm1 = fmaxf(tm1, __shfl_xor_sync(0xffffffff, tm1, 2));

            const float mn0 = fmaxf(m0, tm0);
            const float mn1 = fmaxf(m1, tm1);
            const float sc0 = __expf(m0 - mn0);
            const float sc1 = __expf(m1 - mn1);

            float rs0 = 0.f, rs1 = 0.f;
#pragma unroll
            for (int nf = 0; nf < 8; nf++) {
                sacc[nf][0] = __expf(sacc[nf][0] - mn0);
                sacc[nf][1] = __expf(sacc[nf][1] - mn0);
                sacc[nf][2] = __expf(sacc[nf][2] - mn1);
                sacc[nf][3] = __expf(sacc[nf][3] - mn1);
                rs0 += sacc[nf][0] + sacc[nf][1];
                rs1 += sacc[nf][2] + sacc[nf][3];
            }
            rs0 += __shfl_xor_sync(0xffffffff, rs0, 1);
            rs0 += __shfl_xor_sync(0xffffffff, rs0, 2);
            rs1 += __shfl_xor_sync(0xffffffff, rs1, 1);
            rs1 += __shfl_xor_sync(0xffffffff, rs1, 2);

            l0 = l0 * sc0 + rs0;  m0 = mn0;
            l1 = l1 * sc1 + rs1;  m1 = mn1;
#pragma unroll
            for (int nf = 0; nf < 8; nf++) {
                oacc[nf][0] *= sc0; oacc[nf][1] *= sc0;
                oacc[nf][2] *= sc1; oacc[nf][3] *= sc1;
            }

            const int base = lane & ~3;
            const int s0l  = base + (cg >> 1);
            const int s1l  = s0l + 2;
            const bool odd = (cg & 1);
#pragma unroll
            for (int ks = 0; ks < 8; ks++) {
                const uint32_t c0 = f2tf32(sacc[ks][0]);
                const uint32_t c1 = f2tf32(sacc[ks][1]);
                const uint32_t c2 = f2tf32(sacc[ks][2]);
                const uint32_t c3 = f2tf32(sacc[ks][3]);
                uint32_t a[4];
                {
                    uint32_t t00 = __shfl_sync(0xffffffff, c0, s0l);
                    uint32_t t01 = __shfl_sync(0xffffffff, c1, s0l);
                    uint32_t t10 = __shfl_sync(0xffffffff, c0, s1l);
                    uint32_t t11 = __shfl_sync(0xffffffff, c1, s1l);
                    a[0] = odd ? t01 : t00;
                    a[2] = odd ? t11 : t10;
                    uint32_t u00 = __shfl_sync(0xffffffff, c2, s0l);
                    uint32_t u01 = __shfl_sync(0xffffffff, c3, s0l);
                    uint32_t u10 = __shfl_sync(0xffffffff, c2, s1l);
                    uint32_t u11 = __shfl_sync(0xffffffff, c3, s1l);
                    a[1] = odd ? u01 : u00;
                    a[3] = odd ? u11 : u10;
                }
#pragma unroll
                for (int nf = 0; nf < 8; nf++) {
                    uint32_t b[2];
                    const uint32_t* vp = &Vs[(ks * 8 + cg) * VS_STR + nf * 8 + g];
                    b[0] = vp[0];
                    b[1] = vp[4 * VS_STR];
                    mma_tf32(oacc[nf], a, b);
                }
            }
        }
        __syncthreads();
    }

    const float inv0 = 1.f / l0;
    const float inv1 = 1.f / l1;
    float* o0 = &g_o[(size_t)row0 * DQ + head * HD];
    float* o1 = o0 + 8 * DQ;
#pragma unroll
    for (int nf = 0; nf < 8; nf++) {
        *reinterpret_cast<float2*>(&o0[nf * 8 + 2 * cg]) =
            make_float2(__uint_as_float(f2tf32(oacc[nf][0] * inv0)),
                        __uint_as_float(f2tf32(oacc[nf][1] * inv0)));
        *reinterpret_cast<float2*>(&o1[nf * 8 + 2 * cg]) =
            make_float2(__uint_as_float(f2tf32(oacc[nf][2] * inv1)),
                        __uint_as_float(f2tf32(oacc[nf][3] * inv1)));
    }
}

// ============================================================
extern "C" void kernel_launch(void* const* d_in, const int* in_sizes, int n_in,
                              void* d_out, int out_size) {
    const float* hs   = (const float*)d_in[0];
    const float* cosb = (const float*)d_in[1];
    const float* sinb = (const float*)d_in[2];
    // d_in[3] = attention_mask (causal) — implemented analytically
    const float* wq   = (const float*)d_in[4];
    const float* wk   = (const float*)d_in[5];
    const float* wv   = (const float*)d_in[6];
    const float* wo   = (const float*)d_in[7];
    float* out = (float*)d_out;

    float *op, *woT;
    cudaGetSymbolAddress((void**)&op,  g_o);
    cudaGetSymbolAddress((void**)&woT, g_woT);

    const int gemm_smem  = GK_STAGES * 2 * GK_TILE * (int)sizeof(float);  // 110592 B
    const int flash_smem = 2 * FSTAGE * (int)sizeof(float);               // 71680 B
    cudaFuncSetAttribute(qkv_gemm,   cudaFuncAttributeMaxDynamicSharedMemorySize, gemm_smem);
    cudaFuncSetAttribute(gemm_tf32,  cudaFuncAttributeMaxDynamicSharedMemorySize, gemm_smem);
    cudaFuncSetAttribute(flash_tf32, cudaFuncAttributeMaxDynamicSharedMemorySize, flash_smem);

    // single fused fp32 -> tf32-bits conversion
    const int CB = 256;
    cvt_all<<<(CVT_ALL + CB - 1) / CB, CB>>>(hs, wq, wk, wv, wo);

    // fused QKV projection + RoPE + scale (3-stage pipeline)
    qkv_gemm<<<dim3(DQKV / 128, S_LEN / 128), 256, gemm_smem>>>(cosb, sinb);

    // TF32 causal flash attention (R8 version)
    flash_tf32<<<dim3(S_LEN / 128, NH), 256, flash_smem>>>();

    // output projection (3-stage pipeline)
    gemm_tf32<<<dim3(HID / 128, S_LEN / 128), 256, gemm_smem>>>(op, woT, out, S_LEN, HID, HID);
}

// round 16
// speedup vs baseline: 1.0486x; 1.0321x over previous
#include <cuda_runtime.h>
#include <stdint.h>
#include <math.h>

#define S_LEN 2048
#define HID   2048
#define NH    32
#define NKV   8
#define HD    64
#define DQ    (NH * HD)    // 2048
#define DKV   (NKV * HD)   // 512
#define DQKV  (DQ + 2 * DKV)
#define NEG_HUGE (-1e30f)

// -------- scratch (no dynamic allocation allowed) --------
__device__ float g_q[S_LEN * DQ];       // 16 MB  tf32 bits
__device__ float g_k[S_LEN * DKV];      //  4 MB  tf32 bits
__device__ float g_v[S_LEN * DKV];      //  4 MB  tf32 bits
__device__ float g_o[S_LEN * DQ];       // 16 MB  tf32 bits
__device__ float g_hsT[S_LEN * HID];    // 16 MB  tf32(hs)
__device__ float g_wqkvT[DQKV * HID];   // 24 MB  tf32(wq|wk|wv)
__device__ float g_woT[HID * HID];      // 16 MB  tf32(wo)

// ============================================================
// TF32 helpers
// ============================================================
__device__ __forceinline__ uint32_t f2tf32(float x) {
    uint32_t u;
    asm("cvt.rna.tf32.f32 %0, %1;" : "=r"(u) : "f"(x));
    return u;
}

__device__ __forceinline__ void mma_tf32(float c[4], const uint32_t a[4], const uint32_t b[2]) {
    asm volatile(
        "mma.sync.aligned.m16n8k8.row.col.f32.tf32.tf32.f32 "
        "{%0,%1,%2,%3}, {%4,%5,%6,%7}, {%8,%9}, {%0,%1,%2,%3};"
        : "+f"(c[0]), "+f"(c[1]), "+f"(c[2]), "+f"(c[3])
        : "r"(a[0]), "r"(a[1]), "r"(a[2]), "r"(a[3]),
          "r"(b[0]), "r"(b[1]));
}

__device__ __forceinline__ void cp_async16(uint32_t smem_dst, const void* gmem_src) {
    asm volatile("cp.async.cg.shared.global [%0], [%1], 16;" :: "r"(smem_dst), "l"(gmem_src));
}

// ============================================================
// Fused one-shot fp32 -> tf32-bits conversion for all 5 tensors
// ============================================================
#define CVT_HS  (S_LEN * HID / 4)
#define CVT_WQ  (CVT_HS + DQ * HID / 4)
#define CVT_WK  (CVT_WQ + DKV * HID / 4)
#define CVT_WV  (CVT_WK + DKV * HID / 4)
#define CVT_ALL (CVT_WV + HID * HID / 4)

__global__ void cvt_all(const float* __restrict__ hs,
                        const float* __restrict__ wq,
                        const float* __restrict__ wk,
                        const float* __restrict__ wv,
                        const float* __restrict__ wo) {
    int i = blockIdx.x * blockDim.x + threadIdx.x;
    if (i >= CVT_ALL) return;
    const float* src;
    float* dst;
    int local;
    if (i < CVT_HS)      { src = hs; dst = g_hsT;  local = i; }
    else if (i < CVT_WQ) { src = wq; dst = g_wqkvT; local = i - CVT_HS; }
    else if (i < CVT_WK) { src = wk; dst = g_wqkvT + (size_t)DQ * HID;          local = i - CVT_WQ; }
    else if (i < CVT_WV) { src = wv; dst = g_wqkvT + (size_t)(DQ + DKV) * HID;  local = i - CVT_WK; }
    else                 { src = wo; dst = g_woT;  local = i - CVT_WV; }
    float4 v = reinterpret_cast<const float4*>(src)[local];
    uint4 u;
    u.x = f2tf32(v.x); u.y = f2tf32(v.y); u.z = f2tf32(v.z); u.w = f2tf32(v.w);
    reinterpret_cast<uint4*>(dst)[local] = u;
}

#define GK_PAD 36
#define GK_TILE (128 * GK_PAD)
#define GK_STAGES 3

// ============================================================
// Fused QKV projection + RoPE + scaling.
// 3-stage cp.async ring, ONE __syncthreads per K-iteration,
// regs capped at 128 for 2 CTAs/SM.
// ============================================================
__global__ __launch_bounds__(256, 2) void qkv_gemm(const float* __restrict__ cosb,
                                                   const float* __restrict__ sinb) {
    extern __shared__ float sm[];
    const int tid    = threadIdx.x;
    const int lane   = tid & 31;
    const int wid    = tid >> 5;
    const int warp_m = wid & 3;
    const int warp_n = wid >> 2;
    const int g      = lane >> 2;
    const int cg     = lane & 3;
    const int brow   = blockIdx.y * 128;
    const int bcol   = blockIdx.x * 128;

    const int seg = (bcol < DQ) ? 0 : ((bcol < DQ + DKV) ? 1 : 2);
    const int segbase = (seg == 0) ? 0 : ((seg == 1) ? DQ : DQ + DKV);
    const int out_col = bcol - segbase;
    const int out_ld  = (seg == 0) ? DQ : DKV;
    const bool do_rope = (seg != 2);
    const float scale  = (seg == 0) ? 0.125f : 1.0f;
    float* out = (seg == 0) ? g_q : (seg == 1) ? g_k : g_v;

    float acc[2][8][4];
#pragma unroll
    for (int i = 0; i < 2; i++)
#pragma unroll
        for (int j = 0; j < 8; j++)
#pragma unroll
            for (int t = 0; t < 4; t++) acc[i][j][t] = 0.f;

    auto prefetch = [&](int s, int tile) {
        float* As = sm + s * (2 * GK_TILE);
        float* Bs = As + GK_TILE;
        uint32_t as_base = (uint32_t)__cvta_generic_to_shared(As);
        uint32_t bs_base = (uint32_t)__cvta_generic_to_shared(Bs);
        const int k0 = tile * 32;
#pragma unroll
        for (int i = 0; i < 4; i++) {
            int idx = i * 256 + tid;
            int r   = idx >> 3;
            int c4  = idx & 7;
            cp_async16(as_base + (r * GK_PAD + c4 * 4) * 4,
                       &g_hsT[(size_t)(brow + r) * HID + k0 + c4 * 4]);
            cp_async16(bs_base + (r * GK_PAD + c4 * 4) * 4,
                       &g_wqkvT[(size_t)(bcol + r) * HID + k0 + c4 * 4]);
        }
        asm volatile("cp.async.commit_group;");
    };

    const int NT = HID / 32;   // 64
    prefetch(0, 0);
    prefetch(1, 1);

    for (int i = 0; i < NT; i++) {
        const int s = i % GK_STAGES;
        if (i + 1 < NT) asm volatile("cp.async.wait_group 1;");
        else            asm volatile("cp.async.wait_group 0;");
        __syncthreads();
        if (i + 2 < NT) prefetch((i + 2) % GK_STAGES, i + 2);

        const uint32_t* As = reinterpret_cast<const uint32_t*>(sm + s * (2 * GK_TILE));
        const uint32_t* Bs = As + GK_TILE;

#pragma unroll
        for (int kk = 0; kk < 4; kk++) {
            const int kb = kk * 8;
            uint32_t Af[2][4], Bf[8][2];
#pragma unroll
            for (int mt = 0; mt < 2; mt++) {
                const uint32_t* p = &As[(warp_m * 32 + mt * 16 + g) * GK_PAD + kb + cg];
                Af[mt][0] = p[0];
                Af[mt][1] = p[8 * GK_PAD];
                Af[mt][2] = p[4];
                Af[mt][3] = p[8 * GK_PAD + 4];
            }
#pragma unroll
            for (int nt = 0; nt < 8; nt++) {
                const uint32_t* p = &Bs[(warp_n * 64 + nt * 8 + g) * GK_PAD + kb + cg];
                Bf[nt][0] = p[0];
                Bf[nt][1] = p[4];
            }
#pragma unroll
            for (int mt = 0; mt < 2; mt++)
#pragma unroll
                for (int nt = 0; nt < 8; nt++)
                    mma_tf32(acc[mt][nt], Af[mt], Bf[nt]);
        }
    }

#pragma unroll
    for (int mt = 0; mt < 2; mt++) {
        const int r0 = brow + warp_m * 32 + mt * 16 + g;
        if (do_rope) {
            const float* cb0 = cosb + r0 * HD;
            const float* sb0 = sinb + r0 * HD;
            const float* cb1 = cosb + (r0 + 8) * HD;
            const float* sb1 = sinb + (r0 + 8) * HD;
#pragma unroll
            for (int nt = 0; nt < 4; nt++) {
                const int d = nt * 8 + 2 * cg;
#pragma unroll
                for (int e = 0; e < 2; e++) {
                    const float cl0 = __ldg(cb0 + d + e);
                    const float sl0 = __ldg(sb0 + d + e);
                    const float ch0 = __ldg(cb0 + d + e + 32);
                    const float sh0 = __ldg(sb0 + d + e + 32);
                    const float cl1 = __ldg(cb1 + d + e);
                    const float sl1 = __ldg(sb1 + d + e);
                    const float ch1 = __ldg(cb1 + d + e + 32);
                    const float sh1 = __ldg(sb1 + d + e + 32);

                    const float x1 = acc[mt][nt][e],     x2 = acc[mt][nt + 4][e];
                    acc[mt][nt][e]     = (x1 * cl0 - x2 * sl0) * scale;
                    acc[mt][nt + 4][e] = (x2 * ch0 + x1 * sh0) * scale;
                    const float y1 = acc[mt][nt][e + 2], y2 = acc[mt][nt + 4][e + 2];
                    acc[mt][nt][e + 2]     = (y1 * cl1 - y2 * sl1) * scale;
                    acc[mt][nt + 4][e + 2] = (y2 * ch1 + y1 * sh1) * scale;
                }
            }
        }
        float* orow0 = out + (size_t)r0 * out_ld + out_col + warp_n * 64;
        float* orow1 = orow0 + (size_t)8 * out_ld;
#pragma unroll
        for (int nt = 0; nt < 8; nt++) {
            const int c = nt * 8 + 2 * cg;
            *reinterpret_cast<float2*>(orow0 + c) =
                make_float2(__uint_as_float(f2tf32(acc[mt][nt][0])),
                            __uint_as_float(f2tf32(acc[mt][nt][1])));
            *reinterpret_cast<float2*>(orow1 + c) =
                make_float2(__uint_as_float(f2tf32(acc[mt][nt][2])),
                            __uint_as_float(f2tf32(acc[mt][nt][3])));
        }
    }
}

// ============================================================
// O-projection: C = A * B^T, tf32 bits in, fp32 out.
// 3-stage cp.async ring, ONE __syncthreads per K-iteration,
// regs capped at 128 for 2 CTAs/SM.
// ============================================================
__global__ __launch_bounds__(256, 2) void gemm_tf32(const float* __restrict__ A,
                                                    const float* __restrict__ B,
                                                    float* __restrict__ C,
                                                    int M, int N, int K) {
    extern __shared__ float sm[];
    const int tid    = threadIdx.x;
    const int lane   = tid & 31;
    const int wid    = tid >> 5;
    const int warp_m = wid >> 2;
    const int warp_n = wid & 3;
    const int g      = lane >> 2;
    const int cg     = lane & 3;
    const int brow   = blockIdx.y * 128;
    const int bcol   = blockIdx.x * 128;

    float acc[4][4][4];
#pragma unroll
    for (int i = 0; i < 4; i++)
#pragma unroll
        for (int j = 0; j < 4; j++)
#pragma unroll
            for (int t = 0; t < 4; t++) acc[i][j][t] = 0.f;

    auto prefetch = [&](int s, int tile) {
        float* As = sm + s * (2 * GK_TILE);
        float* Bs = As + GK_TILE;
        uint32_t as_base = (uint32_t)__cvta_generic_to_shared(As);
        uint32_t bs_base = (uint32_t)__cvta_generic_to_shared(Bs);
        const int k0 = tile * 32;
#pragma unroll
        for (int i = 0; i < 4; i++) {
            int idx = i * 256 + tid;
            int r   = idx >> 3;
            int c4  = idx & 7;
            cp_async16(as_base + (r * GK_PAD + c4 * 4) * 4,
                       &A[(size_t)(brow + r) * K + k0 + c4 * 4]);
            cp_async16(bs_base + (r * GK_PAD + c4 * 4) * 4,
                       &B[(size_t)(bcol + r) * K + k0 + c4 * 4]);
        }
        asm volatile("cp.async.commit_group;");
    };

    const int NT = K / 32;
    prefetch(0, 0);
    prefetch(1, 1);

    for (int i = 0; i < NT; i++) {
        const int s = i % GK_STAGES;
        if (i + 1 < NT) asm volatile("cp.async.wait_group 1;");
        else            asm volatile("cp.async.wait_group 0;");
        __syncthreads();
        if (i + 2 < NT) prefetch((i + 2) % GK_STAGES, i + 2);

        const uint32_t* As = reinterpret_cast<const uint32_t*>(sm + s * (2 * GK_TILE));
        const uint32_t* Bs = As + GK_TILE;

#pragma unroll
        for (int kk = 0; kk < 4; kk++) {
            const int kb = kk * 8;
            uint32_t Af[4][4], Bf[4][2];
#pragma unroll
            for (int mt = 0; mt < 4; mt++) {
                const uint32_t* p = &As[(warp_m * 64 + mt * 16 + g) * GK_PAD + kb + cg];
                Af[mt][0] = p[0];
                Af[mt][1] = p[8 * GK_PAD];
                Af[mt][2] = p[4];
                Af[mt][3] = p[8 * GK_PAD + 4];
            }
#pragma unroll
            for (int nt = 0; nt < 4; nt++) {
                const uint32_t* p = &Bs[(warp_n * 32 + nt * 8 + g) * GK_PAD + kb + cg];
                Bf[nt][0] = p[0];
                Bf[nt][1] = p[4];
            }
#pragma unroll
            for (int mt = 0; mt < 4; mt++)
#pragma unroll
                for (int nt = 0; nt < 4; nt++)
                    mma_tf32(acc[mt][nt], Af[mt], Bf[nt]);
        }
    }

#pragma unroll
    for (int mt = 0; mt < 4; mt++) {
#pragma unroll
        for (int nt = 0; nt < 4; nt++) {
            int row0 = brow + warp_m * 64 + mt * 16 + g;
            int col  = bcol + warp_n * 32 + nt * 8 + 2 * cg;
            float2 v0 = make_float2(acc[mt][nt][0], acc[mt][nt][1]);
            float2 v1 = make_float2(acc[mt][nt][2], acc[mt][nt][3]);
            *reinterpret_cast<float2*>(&C[(size_t)row0 * N + col])       = v0;
            *reinterpret_cast<float2*>(&C[(size_t)(row0 + 8) * N + col]) = v1;
        }
    }
}

// ============================================================
// TF32 flash attention (byte-exact R8 version, known-good)
// ============================================================
#define KS_STR 68
#define VS_STR 72
#define FSTAGE (64 * KS_STR + 64 * VS_STR)

__global__ __launch_bounds__(256) void flash_tf32() {
    extern __shared__ float sm[];
    const int tid  = threadIdx.x;
    const int lane = tid & 31;
    const int w    = tid >> 5;
    const int g    = lane >> 2;
    const int cg   = lane & 3;
    const int qt   = gridDim.x - 1 - blockIdx.x;
    const int head = blockIdx.y;
    const int kvh  = head >> 2;
    const int row0 = qt * 128 + w * 16 + g;

    uint32_t qf[8][4];
    {
        const uint32_t* q0 = reinterpret_cast<const uint32_t*>(&g_q[(size_t)row0 * DQ + head * HD]);
        const uint32_t* q1 = q0 + 8 * DQ;
#pragma unroll
        for (int ks = 0; ks < 8; ks++) {
            qf[ks][0] = q0[8 * ks + cg];
            qf[ks][1] = q1[8 * ks + cg];
            qf[ks][2] = q0[8 * ks + cg + 4];
            qf[ks][3] = q1[8 * ks + cg + 4];
        }
    }

    float oacc[8][4];
#pragma unroll
    for (int nf = 0; nf < 8; nf++)
#pragma unroll
        for (int t = 0; t < 4; t++) oacc[nf][t] = 0.f;
    float m0 = NEG_HUGE, m1 = NEG_HUGE, l0 = 0.f, l1 = 0.f;

    auto prefetch = [&](int kb, int s) {
        float* Ks = sm + s * FSTAGE;
        float* Vs = Ks + 64 * KS_STR;
        uint32_t ka = (uint32_t)__cvta_generic_to_shared(Ks);
        uint32_t va = (uint32_t)__cvta_generic_to_shared(Vs);
#pragma unroll
        for (int t = 0; t < 4; t++) {
            int idx = t * 256 + tid;
            int r   = idx >> 4;
            int c4  = (idx & 15) * 4;
            cp_async16(ka + (r * KS_STR + c4) * 4,
                       &g_k[(size_t)(kb * 64 + r) * DKV + kvh * HD + c4]);
            cp_async16(va + (r * VS_STR + c4) * 4,
                       &g_v[(size_t)(kb * 64 + r) * DKV + kvh * HD + c4]);
        }
        asm volatile("cp.async.commit_group;");
    };

    const int nkb = 2 * qt + 2;
    prefetch(0, 0);

    for (int kb = 0; kb < nkb; kb++) {
        const int s = kb & 1;
        if (kb + 1 < nkb) {
            prefetch(kb + 1, s ^ 1);
            asm volatile("cp.async.wait_group 1;");
        } else {
            asm volatile("cp.async.wait_group 0;");
        }
        __syncthreads();

        const uint32_t* Ks = reinterpret_cast<const uint32_t*>(sm + s * FSTAGE);
        const uint32_t* Vs = Ks + 64 * KS_STR;

        const bool active = !(w < 4 && kb == 2 * qt + 1);
        if (active) {
            float sacc[8][4];
#pragma unroll
            for (int nf = 0; nf < 8; nf++)
#pragma unroll
                for (int t = 0; t < 4; t++) sacc[nf][t] = 0.f;

#pragma unroll
            for (int ks = 0; ks < 8; ks++) {
#pragma unroll
                for (int nf = 0; nf < 8; nf++) {
                    uint32_t b[2];
                    const uint32_t* p = &Ks[(nf * 8 + g) * KS_STR + ks * 8 + cg];
                    b[0] = p[0];
                    b[1] = p[4];
                    mma_tf32(sacc[nf], qf[ks], b);
                }
            }

            if (kb >= 2 * qt) {
#pragma unroll
                for (int nf = 0; nf < 8; nf++) {
                    int c = kb * 64 + nf * 8 + 2 * cg;
                    if (c     > row0)     sacc[nf][0] = NEG_HUGE;
                    if (c + 1 > row0)     sacc[nf][1] = NEG_HUGE;
                    if (c     > row0 + 8) sacc[nf][2] = NEG_HUGE;
                    if (c + 1 > row0 + 8) sacc[nf][3] = NEG_HUGE;
                }
            }

            float tm0 = NEG_HUGE, tm1 = NEG_HUGE;
#pragma unroll
            for (int nf = 0; nf < 8; nf++) {
                tm0 = fmaxf(tm0, fmaxf(sacc[nf][0], sacc[nf][1]));
                tm1 = fmaxf(tm1, fmaxf(sacc[nf][2], sacc[nf][3]));
            }
            tm0 = fmaxf(tm0, __shfl_xor_sync(0xffffffff, tm0, 1));
            tm0 = fmaxf(tm0, __shfl_xor_sync(0xffffffff, tm0, 2));
            tm1 = fmaxf(tm1, __shfl_xor_sync(0xffffffff, tm1, 1));
            tm1 = fmaxf(tm1, __shfl_xor_sync(0xffffffff, tm1, 2));

            const float mn0 = fmaxf(m0, tm0);
            const float mn1 = fmaxf(m1, tm1);
            const float sc0 = __expf(m0 - mn0);
            const float sc1 = __expf(m1 - mn1);

            float rs0 = 0.f, rs1 = 0.f;
#pragma unroll
            for (int nf = 0; nf < 8; nf++) {
                sacc[nf][0] = __expf(sacc[nf][0] - mn0);
                sacc[nf][1] = __expf(sacc[nf][1] - mn0);
                sacc[nf][2] = __expf(sacc[nf][2] - mn1);
                sacc[nf][3] = __expf(sacc[nf][3] - mn1);
                rs0 += sacc[nf][0] + sacc[nf][1];
                rs1 += sacc[nf][2] + sacc[nf][3];
            }
            rs0 += __shfl_xor_sync(0xffffffff, rs0, 1);
            rs0 += __shfl_xor_sync(0xffffffff, rs0, 2);
            rs1 += __shfl_xor_sync(0xffffffff, rs1, 1);
            rs1 += __shfl_xor_sync(0xffffffff, rs1, 2);

            l0 = l0 * sc0 + rs0;  m0 = mn0;
            l1 = l1 * sc1 + rs1;  m1 = mn1;
#pragma unroll
            for (int nf = 0; nf < 8; nf++) {
                oacc[nf][0] *= sc0; oacc[nf][1] *= sc0;
                oacc[nf][2] *= sc1; oacc[nf][3] *= sc1;
            }

            const int base = lane & ~3;
            const int s0l  = base + (cg >> 1);
            const int s1l  = s0l + 2;
            const bool odd = (cg & 1);
#pragma unroll
            for (int ks = 0; ks < 8; ks++) {
                const uint32_t c0 = f2tf32(sacc[ks][0]);
                const uint32_t c1 = f2tf32(sacc[ks][1]);
                const uint32_t c2 = f2tf32(sacc[ks][2]);
                const uint32_t c3 = f2tf32(sacc[ks][3]);
                uint32_t a[4];
                {
                    uint32_t t00 = __shfl_sync(0xffffffff, c0, s0l);
                    uint32_t t01 = __shfl_sync(0xffffffff, c1, s0l);
                    uint32_t t10 = __shfl_sync(0xffffffff, c0, s1l);
                    uint32_t t11 = __shfl_sync(0xffffffff, c1, s1l);
                    a[0] = odd ? t01 : t00;
                    a[2] = odd ? t11 : t10;
                    uint32_t u00 = __shfl_sync(0xffffffff, c2, s0l);
                    uint32_t u01 = __shfl_sync(0xffffffff, c3, s0l);
                    uint32_t u10 = __shfl_sync(0xffffffff, c2, s1l);
                    uint32_t u11 = __shfl_sync(0xffffffff, c3, s1l);
                    a[1] = odd ? u01 : u00;
                    a[3] = odd ? u11 : u10;
                }
#pragma unroll
                for (int nf = 0; nf < 8; nf++) {
                    uint32_t b[2];
                    const uint32_t* vp = &Vs[(ks * 8 + cg) * VS_STR + nf * 8 + g];
                    b[0] = vp[0];
                    b[1] = vp[4 * VS_STR];
                    mma_tf32(oacc[nf], a, b);
                }
            }
        }
        __syncthreads();
    }

    const float inv0 = 1.f / l0;
    const float inv1 = 1.f / l1;
    float* o0 = &g_o[(size_t)row0 * DQ + head * HD];
    float* o1 = o0 + 8 * DQ;
#pragma unroll
    for (int nf = 0; nf < 8; nf++) {
        *reinterpret_cast<float2*>(&o0[nf * 8 + 2 * cg]) =
            make_float2(__uint_as_float(f2tf32(oacc[nf][0] * inv0)),
                        __uint_as_float(f2tf32(oacc[nf][1] * inv0)));
        *reinterpret_cast<float2*>(&o1[nf * 8 + 2 * cg]) =
            make_float2(__uint_as_float(f2tf32(oacc[nf][2] * inv1)),
                        __uint_as_float(f2tf32(oacc[nf][3] * inv1)));
    }
}

// ============================================================
extern "C" void kernel_launch(void* const* d_in, const int* in_sizes, int n_in,
                              void* d_out, int out_size) {
    const float* hs   = (const float*)d_in[0];
    const float* cosb = (const float*)d_in[1];
    const float* sinb = (const float*)d_in[2];
    // d_in[3] = attention_mask (causal) — implemented analytically
    const float* wq   = (const float*)d_in[4];
    const float* wk   = (const float*)d_in[5];
    const float* wv   = (const float*)d_in[6];
    const float* wo   = (const float*)d_in[7];
    float* out = (float*)d_out;

    float *op, *woT;
    cudaGetSymbolAddress((void**)&op,  g_o);
    cudaGetSymbolAddress((void**)&woT, g_woT);

    const int gemm_smem  = GK_STAGES * 2 * GK_TILE * (int)sizeof(float);  // 110592 B
    const int flash_smem = 2 * FSTAGE * (int)sizeof(float);               // 71680 B
    cudaFuncSetAttribute(qkv_gemm,   cudaFuncAttributeMaxDynamicSharedMemorySize, gemm_smem);
    cudaFuncSetAttribute(gemm_tf32,  cudaFuncAttributeMaxDynamicSharedMemorySize, gemm_smem);
    cudaFuncSetAttribute(flash_tf32, cudaFuncAttributeMaxDynamicSharedMemorySize, flash_smem);

    // single fused fp32 -> tf32-bits conversion
    const int CB = 256;
    cvt_all<<<(CVT_ALL + CB - 1) / CB, CB>>>(hs, wq, wk, wv, wo);

    // fused QKV projection + RoPE + scale (3-stage pipeline, 2 CTA/SM)
    qkv_gemm<<<dim3(DQKV / 128, S_LEN / 128), 256, gemm_smem>>>(cosb, sinb);

    // TF32 causal flash attention (R8 version)
    flash_tf32<<<dim3(S_LEN / 128, NH), 256, flash_smem>>>();

    // output projection (3-stage pipeline, 2 CTA/SM)
    gemm_tf32<<<dim3(HID / 128, S_LEN / 128), 256, gemm_smem>>>(op, woT, out, S_LEN, HID, HID);
}